// round 6
// baseline (speedup 1.0000x reference)
#include <cuda_runtime.h>
#include <cuda_fp16.h>
#include <cstdint>

#define NT      17
#define DIN     128
#define NNODES  32768
#define ROWS    128
#define TILES   (NNODES / ROWS)   // 256

#define A_STRIDE_H 136            // A tile stride in halves (272B ≡ 16 mod 128 -> LDSM conflict-free)
#define W_STRIDE_U 136            // W k2-row stride in u32 (conflict-free B-frag LDS)
#define W_TERM_U   (64 * W_STRIDE_U)   // 8704 u32 per term

// smem byte offsets
#define OFF_ROWIDX 0                       // 128*4
#define OFF_B1     512
#define OFF_B2     1024
#define OFF_A      1536                    // 128*272 = 34816
#define OFF_W      (OFF_A + 34816)         // 36352 ; 2 terms * 34816 = 69632
#define SMEM_BYTES (OFF_W + 2 * W_TERM_U * 4)   // 105984

#define WELEMS (NT * 64 * 128)    // 139264 packed u32 per (layer,term)

// ---------------- allocation-free scratch ----------------
__device__ int g_count[NT];
__device__ int g_idx[NT * NNODES];
// Packed fp16x2 W: [layer][type][term hi/lo][k2*128 + n]
__device__ uint32_t g_w[2][NT][2][8192];

// ---------------- helpers ----------------
__device__ __forceinline__ uint32_t smem_u32(const void* p) {
    uint32_t a;
    asm("{ .reg .u64 t; cvta.to.shared.u64 t, %1; cvt.u32.u64 %0, t; }" : "=r"(a) : "l"(p));
    return a;
}

__device__ __forceinline__ void cp16(uint32_t dst, const void* src) {
    asm volatile("cp.async.cg.shared.global [%0], [%1], 16;" :: "r"(dst), "l"(src));
}

__device__ __forceinline__ void ldsm4(uint32_t* r, uint32_t addr) {
    asm volatile("ldmatrix.sync.aligned.m8n8.x4.shared.b16 {%0,%1,%2,%3}, [%4];"
                 : "=r"(r[0]), "=r"(r[1]), "=r"(r[2]), "=r"(r[3]) : "r"(addr));
}

__device__ __forceinline__ void mma_f16(float* c, const uint32_t* a, uint32_t b0, uint32_t b1) {
    asm volatile(
        "mma.sync.aligned.m16n8k16.row.col.f32.f16.f16.f32 "
        "{%0,%1,%2,%3}, {%4,%5,%6,%7}, {%8,%9}, {%0,%1,%2,%3};"
        : "+f"(c[0]), "+f"(c[1]), "+f"(c[2]), "+f"(c[3])
        : "r"(a[0]), "r"(a[1]), "r"(a[2]), "r"(a[3]), "r"(b0), "r"(b1));
}

__device__ __forceinline__ uint32_t packh2(__half a, __half b) {
    __half2 h = __halves2half2(a, b);   // a -> low half (k even first)
    return *reinterpret_cast<uint32_t*>(&h);
}

// ---------------- prep: zero counts + split W into packed fp16 hi/lo ----------------
// Layout per (layer,term): [k2][n] u32 = fp16x2 {low = W[2k2][n], high = W[2k2+1][n]}.
__global__ void prep_kernel(const float* __restrict__ W1, const float* __restrict__ W2) {
    if (blockIdx.x == 0 && threadIdx.x < NT) g_count[threadIdx.x] = 0;
    int idx = blockIdx.x * 256 + threadIdx.x;   // grid = WELEMS/256 = 544, exact
    int t   = idx >> 13;
    int rem = idx & 8191;   // k2*128 + n
    size_t off = (size_t)t * 16384 + (size_t)(rem >> 7) * 256 + (rem & 127);
    {
        float a0 = __ldg(W1 + off), a1 = __ldg(W1 + off + 128);
        __half h0 = __float2half_rn(a0), h1 = __float2half_rn(a1);
        __half l0 = __float2half_rn(a0 - __half2float(h0));
        __half l1 = __float2half_rn(a1 - __half2float(h1));
        g_w[0][t][0][rem] = packh2(h0, h1);
        g_w[0][t][1][rem] = packh2(l0, l1);
    }
    {
        float a0 = __ldg(W2 + off), a1 = __ldg(W2 + off + 128);
        __half h0 = __float2half_rn(a0), h1 = __float2half_rn(a1);
        __half l0 = __float2half_rn(a0 - __half2float(h0));
        __half l1 = __float2half_rn(a1 - __half2float(h1));
        g_w[1][t][0][rem] = packh2(h0, h1);
        g_w[1][t][1][rem] = packh2(l0, l1);
    }
}

__global__ void scatter_kernel(const int* __restrict__ types) {
    int n = blockIdx.x * blockDim.x + threadIdx.x;
    if (n < NNODES) {
        int t = types[n];
        int p = atomicAdd(&g_count[t], 1);
        g_idx[t * NNODES + p] = n;
    }
}

// ---------------- stage one layer's W (hi+lo, 64KB data) via cp.async ----------------
__device__ __forceinline__ void stage_w(int layer, int t, int tid, uint32_t wsm) {
    #pragma unroll
    for (int i = 0; i < 16; i++) {
        int li   = tid + i * 256;        // 0..4095
        int term = li >> 11;             // 2048 cp16 per term
        int r    = (li >> 5) & 63;       // k2-row
        int seg  = li & 31;              // 16B segment within 512B row
        uint32_t dst = wsm + term * (W_TERM_U * 4) + r * (W_STRIDE_U * 4) + seg * 16;
        const char* src = reinterpret_cast<const char*>(g_w[layer][t][term]) + r * 512 + seg * 16;
        cp16(dst, src);
    }
    asm volatile("cp.async.commit_group;" ::: "memory");
}

// ---------------- one 128x128x128 GEMM (fp16 2-term), acc += A @ (Whi + Wlo) ----------------
__device__ __forceinline__ void run_gemm(uint32_t sbase, const uint32_t* __restrict__ Wsm,
                                         float acc[2][8][4], int lane, int mbase, int nbase) {
    int rowA = mbase + ((lane >> 3) & 1) * 8 + (lane & 7);
    uint32_t aAddr = sbase + OFF_A + rowA * (A_STRIDE_H * 2) + (lane >> 4) * 16;
    const int li = lane & 3;
    const int cb = nbase + (lane >> 2);

    #pragma unroll 2
    for (int kc = 0; kc < 8; kc++) {
        uint32_t a[2][4];
        ldsm4(a[0], aAddr + kc * 32);
        ldsm4(a[1], aAddr + 16 * (A_STRIDE_H * 2) + kc * 32);
        int k2b = kc * 8 + li;
        #pragma unroll
        for (int nt = 0; nt < 8; nt++) {
            int col = cb + nt * 8;
            uint32_t bh0 = Wsm[k2b * W_STRIDE_U + col];
            uint32_t bh1 = Wsm[(k2b + 4) * W_STRIDE_U + col];
            uint32_t bl0 = Wsm[W_TERM_U + k2b * W_STRIDE_U + col];
            uint32_t bl1 = Wsm[W_TERM_U + (k2b + 4) * W_STRIDE_U + col];
            mma_f16(acc[0][nt], a[0], bh0, bh1);
            mma_f16(acc[1][nt], a[1], bh0, bh1);
            mma_f16(acc[0][nt], a[0], bl0, bl1);
            mma_f16(acc[1][nt], a[1], bl0, bl1);
        }
    }
}

extern __shared__ __align__(16) char smem[];

__global__ __launch_bounds__(256, 2) void mlp_kernel(
    const float* __restrict__ x,
    const float* __restrict__ b1,
    const float* __restrict__ b2,
    float* __restrict__ out)
{
    const int t    = blockIdx.y;
    const int cnt  = g_count[t];
    const int base = blockIdx.x * ROWS;
    if (base >= cnt) return;

    const uint32_t sbase = smem_u32(smem);
    const int tid  = threadIdx.x;
    const int lane = tid & 31;
    const int warp = tid >> 5;
    const int mbase = (warp >> 1) * 32;
    const int nbase = (warp & 1) * 64;

    int*   rowidx = reinterpret_cast<int*>(smem + OFF_ROWIDX);
    float* sB1    = reinterpret_cast<float*>(smem + OFF_B1);
    float* sB2    = reinterpret_cast<float*>(smem + OFF_B2);
    const uint32_t* Wsm = reinterpret_cast<const uint32_t*>(smem + OFF_W);

    if (tid < ROWS) {
        int r = base + tid;
        rowidx[tid] = (r < cnt) ? g_idx[t * NNODES + r] : -1;
        sB1[tid] = __ldg(b1 + t * DIN + tid);
        sB2[tid] = __ldg(b2 + t * DIN + tid);
    }
    __syncthreads();

    // Issue W1 staging (async), then gather A under it.
    stage_w(0, t, tid, sbase + OFF_W);

    // Gather x rows -> fp16 A tile. thread = (row = tid/2, k-half = tid&1).
    {
        int r = tid >> 1, kh = tid & 1;
        int g = rowidx[r];
        uint32_t* dst = reinterpret_cast<uint32_t*>(smem + OFF_A + r * (A_STRIDE_H * 2) + kh * 128);
        if (g >= 0) {
            const float4* src = reinterpret_cast<const float4*>(x + (size_t)g * DIN + kh * 64);
            #pragma unroll
            for (int i = 0; i < 16; i++) {
                float4 v = __ldg(src + i);
                __half2 p0 = __floats2half2_rn(v.x, v.y);
                __half2 p1 = __floats2half2_rn(v.z, v.w);
                dst[2 * i]     = *reinterpret_cast<uint32_t*>(&p0);
                dst[2 * i + 1] = *reinterpret_cast<uint32_t*>(&p1);
            }
        } else {
            #pragma unroll
            for (int i = 0; i < 32; i++) dst[i] = 0u;
        }
    }

    asm volatile("cp.async.wait_group 0;" ::: "memory");
    __syncthreads();

    float acc[2][8][4];
    #pragma unroll
    for (int s = 0; s < 2; s++)
        #pragma unroll
        for (int nt = 0; nt < 8; nt++)
            #pragma unroll
            for (int i = 0; i < 4; i++) acc[s][nt][i] = 0.f;

    // ---------------- Layer 1 ----------------
    run_gemm(sbase, Wsm, acc, lane, mbase, nbase);

    __syncthreads();                    // all A + W1 reads done
    stage_w(1, t, tid, sbase + OFF_W);  // overlap W2 copy with epilogue

    // epilogue 1: bias + relu -> fp16 back into A tile, reset acc
    #pragma unroll
    for (int s = 0; s < 2; s++) {
        #pragma unroll
        for (int nt = 0; nt < 8; nt++) {
            int col = nbase + nt * 8 + 2 * (lane & 3);
            float bb0 = sB1[col], bb1 = sB1[col + 1];
            int r0 = mbase + s * 16 + (lane >> 2);
            __half2 v0 = __floats2half2_rn(fmaxf(acc[s][nt][0] + bb0, 0.f),
                                           fmaxf(acc[s][nt][1] + bb1, 0.f));
            __half2 v1 = __floats2half2_rn(fmaxf(acc[s][nt][2] + bb0, 0.f),
                                           fmaxf(acc[s][nt][3] + bb1, 0.f));
            *reinterpret_cast<__half2*>(smem + OFF_A + r0 * (A_STRIDE_H * 2) + col * 2) = v0;
            *reinterpret_cast<__half2*>(smem + OFF_A + (r0 + 8) * (A_STRIDE_H * 2) + col * 2) = v1;
            acc[s][nt][0] = acc[s][nt][1] = acc[s][nt][2] = acc[s][nt][3] = 0.f;
        }
    }

    asm volatile("cp.async.wait_group 0;" ::: "memory");
    __syncthreads();                    // H visible + W2 staged

    // ---------------- Layer 2 ----------------
    run_gemm(sbase, Wsm, acc, lane, mbase, nbase);

    // epilogue 2: bias -> scatter to out
    #pragma unroll
    for (int s = 0; s < 2; s++) {
        #pragma unroll
        for (int nt = 0; nt < 8; nt++) {
            int col = nbase + nt * 8 + 2 * (lane & 3);
            float bb0 = sB2[col], bb1 = sB2[col + 1];
            int r0 = mbase + s * 16 + (lane >> 2);
            int g0 = rowidx[r0];
            int g1 = rowidx[r0 + 8];
            if (g0 >= 0)
                *reinterpret_cast<float2*>(out + (size_t)g0 * DIN + col) =
                    make_float2(acc[s][nt][0] + bb0, acc[s][nt][1] + bb1);
            if (g1 >= 0)
                *reinterpret_cast<float2*>(out + (size_t)g1 * DIN + col) =
                    make_float2(acc[s][nt][2] + bb0, acc[s][nt][3] + bb1);
        }
    }
}

extern "C" void kernel_launch(void* const* d_in, const int* in_sizes, int n_in,
                              void* d_out, int out_size)
{
    const float* x     = (const float*)d_in[0];
    const float* W1    = (const float*)d_in[1];
    const float* b1    = (const float*)d_in[2];
    const float* W2    = (const float*)d_in[3];
    const float* b2    = (const float*)d_in[4];
    const int*   types = (const int*)  d_in[5];
    float*       out   = (float*)d_out;

    cudaFuncSetAttribute(mlp_kernel, cudaFuncAttributeMaxDynamicSharedMemorySize, SMEM_BYTES);

    prep_kernel<<<WELEMS / 256, 256>>>(W1, W2);
    scatter_kernel<<<NNODES / 256, 256>>>(types);
    dim3 grid(TILES, NT);
    mlp_kernel<<<grid, 256, SMEM_BYTES>>>(x, b1, b2, out);
}

// round 9
// speedup vs baseline: 1.7543x; 1.7543x over previous
#include <cuda_runtime.h>
#include <cuda_fp16.h>
#include <cstdint>

#define NT      17
#define DIN     128
#define NNODES  32768
#define ROWS    128
#define MAXWORK 274

#define A_STRIDE_H 136            // A tile stride in halves (272B)
#define W_STRIDE_U 136            // W k2-row stride in u32
#define W_TERM_U   (64 * W_STRIDE_U)   // 8704 u32 per term

// smem byte offsets
#define OFF_ROWIDX 0
#define OFF_B1     512
#define OFF_B2     1024
#define OFF_A      1536                    // 128*272 = 34816
#define OFF_W      (OFF_A + 34816)         // 2 terms * 34816
#define SMEM_BYTES (OFF_W + 2 * W_TERM_U * 4)   // 105984

#define WELEMS (NT * 64 * 128)    // 139264

// ---------------- allocation-free scratch ----------------
__device__ int g_count[NT];
__device__ int g_idx[NT * NNODES];
__device__ uint32_t g_w[2][NT][2][8192];
__device__ int g_nwork;
__device__ int g_work[MAXWORK];

// ---------------- helpers ----------------
__device__ __forceinline__ uint32_t smem_u32(const void* p) {
    uint32_t a;
    asm("{ .reg .u64 t; cvta.to.shared.u64 t, %1; cvt.u32.u64 %0, t; }" : "=r"(a) : "l"(p));
    return a;
}

__device__ __forceinline__ void cp16(uint32_t dst, const void* src) {
    asm volatile("cp.async.cg.shared.global [%0], [%1], 16;" :: "r"(dst), "l"(src));
}

__device__ __forceinline__ void ldsm4(uint32_t* r, uint32_t addr) {
    asm volatile("ldmatrix.sync.aligned.m8n8.x4.shared.b16 {%0,%1,%2,%3}, [%4];"
                 : "=r"(r[0]), "=r"(r[1]), "=r"(r[2]), "=r"(r[3]) : "r"(addr));
}

__device__ __forceinline__ void mma_f16(float* c, const uint32_t* a, uint32_t b0, uint32_t b1) {
    asm volatile(
        "mma.sync.aligned.m16n8k16.row.col.f32.f16.f16.f32 "
        "{%0,%1,%2,%3}, {%4,%5,%6,%7}, {%8,%9}, {%0,%1,%2,%3};"
        : "+f"(c[0]), "+f"(c[1]), "+f"(c[2]), "+f"(c[3])
        : "r"(a[0]), "r"(a[1]), "r"(a[2]), "r"(a[3]), "r"(b0), "r"(b1));
}

__device__ __forceinline__ uint32_t packh2(__half a, __half b) {
    __half2 h = __halves2half2(a, b);
    return *reinterpret_cast<uint32_t*>(&h);
}

// ---------------- prep ----------------
__global__ void prep_kernel(const float* __restrict__ W1, const float* __restrict__ W2) {
    if (blockIdx.x == 0 && threadIdx.x < NT) g_count[threadIdx.x] = 0;
    int idx = blockIdx.x * 256 + threadIdx.x;
    int t   = idx >> 13;
    int rem = idx & 8191;
    size_t off = (size_t)t * 16384 + (size_t)(rem >> 7) * 256 + (rem & 127);
    {
        float a0 = __ldg(W1 + off), a1 = __ldg(W1 + off + 128);
        __half h0 = __float2half_rn(a0), h1 = __float2half_rn(a1);
        __half l0 = __float2half_rn(a0 - __half2float(h0));
        __half l1 = __float2half_rn(a1 - __half2float(h1));
        g_w[0][t][0][rem] = packh2(h0, h1);
        g_w[0][t][1][rem] = packh2(l0, l1);
    }
    {
        float a0 = __ldg(W2 + off), a1 = __ldg(W2 + off + 128);
        __half h0 = __float2half_rn(a0), h1 = __float2half_rn(a1);
        __half l0 = __float2half_rn(a0 - __half2float(h0));
        __half l1 = __float2half_rn(a1 - __half2float(h1));
        g_w[1][t][0][rem] = packh2(h0, h1);
        g_w[1][t][1][rem] = packh2(l0, l1);
    }
}

// ---------------- two-level scatter ----------------
__global__ void scatter_kernel(const int* __restrict__ types) {
    __shared__ int scount[NT];
    __shared__ int sbase_[NT];
    int tid = threadIdx.x;
    if (tid < NT) scount[tid] = 0;
    __syncthreads();
    int n = blockIdx.x * blockDim.x + tid;
    int t = types[n];
    int rank = atomicAdd(&scount[t], 1);
    __syncthreads();
    if (tid < NT) sbase_[tid] = atomicAdd(&g_count[tid], scount[tid]);
    __syncthreads();
    g_idx[t * NNODES + sbase_[t] + rank] = n;
}

// ---------------- plan: counts -> compact worklist ----------------
__global__ void plan_kernel() {
    __shared__ int pref[NT + 1];
    if (threadIdx.x == 0) {
        int w = 0;
        for (int t = 0; t < NT; t++) {
            pref[t] = w;
            w += (g_count[t] + ROWS - 1) / ROWS;
        }
        pref[NT] = w;
        g_nwork = w;
    }
    __syncwarp();
    for (int t = 0; t < NT; t++) {
        int s = pref[t], e = pref[t + 1];
        for (int i = s + (int)threadIdx.x; i < e; i += 32)
            g_work[i] = (t << 16) | (i - s);
    }
}

// ---------------- W staging via cp.async ----------------
__device__ __forceinline__ void stage_w(int layer, int t, int tid, uint32_t wsm) {
    #pragma unroll
    for (int i = 0; i < 16; i++) {
        int li   = tid + i * 256;
        int term = li >> 11;
        int r    = (li >> 5) & 63;
        int seg  = li & 31;
        uint32_t dst = wsm + term * (W_TERM_U * 4) + r * (W_STRIDE_U * 4) + seg * 16;
        const char* src = reinterpret_cast<const char*>(g_w[layer][t][term]) + r * 512 + seg * 16;
        cp16(dst, src);
    }
    asm volatile("cp.async.commit_group;" ::: "memory");
}

// ---------------- lean fp16 2-term GEMM ----------------
__device__ __forceinline__ void run_gemm(uint32_t sbase, const uint32_t* __restrict__ Wsm,
                                         float acc[2][8][4], int lane, int mbase, int nbase) {
    int rowA = mbase + ((lane >> 3) & 1) * 8 + (lane & 7);
    uint32_t aAddr = sbase + OFF_A + rowA * (A_STRIDE_H * 2) + (lane >> 4) * 16;
    const int li = lane & 3;
    const int cb = nbase + (lane >> 2);

    #pragma unroll 1
    for (int kc = 0; kc < 8; kc++) {
        uint32_t a0[4], a1[4];
        ldsm4(a0, aAddr + kc * 32);
        ldsm4(a1, aAddr + 16 * (A_STRIDE_H * 2) + kc * 32);
        int k2b = kc * 8 + li;
        const uint32_t* Wh = Wsm + k2b * W_STRIDE_U + cb;
        const uint32_t* Wl = Wh + W_TERM_U;
        #pragma unroll
        for (int nt = 0; nt < 8; nt++) {
            uint32_t b0 = Wh[nt * 8];
            uint32_t b1 = Wh[nt * 8 + 4 * W_STRIDE_U];
            mma_f16(acc[0][nt], a0, b0, b1);
            mma_f16(acc[1][nt], a1, b0, b1);
            b0 = Wl[nt * 8];
            b1 = Wl[nt * 8 + 4 * W_STRIDE_U];
            mma_f16(acc[0][nt], a0, b0, b1);
            mma_f16(acc[1][nt], a1, b0, b1);
        }
    }
}

extern __shared__ __align__(16) char smem[];

__global__ __launch_bounds__(256, 2) void mlp_kernel(
    const float* __restrict__ x,
    const float* __restrict__ b1,
    const float* __restrict__ b2,
    float* __restrict__ out)
{
    if ((int)blockIdx.x >= g_nwork) return;
    const int wk   = g_work[blockIdx.x];
    const int t    = wk >> 16;
    const int base = (wk & 0xFFFF) * ROWS;
    const int cnt  = g_count[t];

    const uint32_t sbase = smem_u32(smem);
    const int tid  = threadIdx.x;
    const int lane = tid & 31;
    const int warp = tid >> 5;
    const int mbase = (warp >> 1) * 32;
    const int nbase = (warp & 1) * 64;

    int*   rowidx = reinterpret_cast<int*>(smem + OFF_ROWIDX);
    float* sB1    = reinterpret_cast<float*>(smem + OFF_B1);
    float* sB2    = reinterpret_cast<float*>(smem + OFF_B2);
    const uint32_t* Wsm = reinterpret_cast<const uint32_t*>(smem + OFF_W);

    stage_w(0, t, tid, sbase + OFF_W);      // async W1 copy under everything below

    if (tid < ROWS) {
        int r = base + tid;
        rowidx[tid] = (r < cnt) ? g_idx[t * NNODES + r] : -1;
        sB1[tid] = __ldg(b1 + t * DIN + tid);
        sB2[tid] = __ldg(b2 + t * DIN + tid);
    }
    __syncthreads();

    // Gather x rows -> fp16 A tile. thread = (row = tid/2, k-half = tid&1).
    {
        int r = tid >> 1, kh = tid & 1;
        int g = rowidx[r];
        uint32_t* dst = reinterpret_cast<uint32_t*>(smem + OFF_A + r * (A_STRIDE_H * 2) + kh * 128);
        if (g >= 0) {
            const float4* src = reinterpret_cast<const float4*>(x + (size_t)g * DIN + kh * 64);
            #pragma unroll
            for (int i = 0; i < 16; i++) {
                float4 v = __ldg(src + i);
                __half2 p0 = __floats2half2_rn(v.x, v.y);
                __half2 p1 = __floats2half2_rn(v.z, v.w);
                dst[2 * i]     = *reinterpret_cast<uint32_t*>(&p0);
                dst[2 * i + 1] = *reinterpret_cast<uint32_t*>(&p1);
            }
        } else {
            #pragma unroll
            for (int i = 0; i < 32; i++) dst[i] = 0u;
        }
    }

    asm volatile("cp.async.wait_group 0;" ::: "memory");
    __syncthreads();

    float acc[2][8][4];
    #pragma unroll
    for (int s = 0; s < 2; s++)
        #pragma unroll
        for (int nt = 0; nt < 8; nt++)
            #pragma unroll
            for (int i = 0; i < 4; i++) acc[s][nt][i] = 0.f;

    // ---------------- Layer 1 ----------------
    run_gemm(sbase, Wsm, acc, lane, mbase, nbase);

    __syncthreads();
    stage_w(1, t, tid, sbase + OFF_W);      // overlap W2 copy with epilogue

    #pragma unroll
    for (int s = 0; s < 2; s++) {
        #pragma unroll
        for (int nt = 0; nt < 8; nt++) {
            int col = nbase + nt * 8 + 2 * (lane & 3);
            float bb0 = sB1[col], bb1 = sB1[col + 1];
            int r0 = mbase + s * 16 + (lane >> 2);
            __half2 v0 = __floats2half2_rn(fmaxf(acc[s][nt][0] + bb0, 0.f),
                                           fmaxf(acc[s][nt][1] + bb1, 0.f));
            __half2 v1 = __floats2half2_rn(fmaxf(acc[s][nt][2] + bb0, 0.f),
                                           fmaxf(acc[s][nt][3] + bb1, 0.f));
            *reinterpret_cast<__half2*>(smem + OFF_A + r0 * (A_STRIDE_H * 2) + col * 2) = v0;
            *reinterpret_cast<__half2*>(smem + OFF_A + (r0 + 8) * (A_STRIDE_H * 2) + col * 2) = v1;
            acc[s][nt][0] = acc[s][nt][1] = acc[s][nt][2] = acc[s][nt][3] = 0.f;
        }
    }

    asm volatile("cp.async.wait_group 0;" ::: "memory");
    __syncthreads();

    // ---------------- Layer 2 ----------------
    run_gemm(sbase, Wsm, acc, lane, mbase, nbase);

    #pragma unroll
    for (int s = 0; s < 2; s++) {
        #pragma unroll
        for (int nt = 0; nt < 8; nt++) {
            int col = nbase + nt * 8 + 2 * (lane & 3);
            float bb0 = sB2[col], bb1 = sB2[col + 1];
            int r0 = mbase + s * 16 + (lane >> 2);
            int g0 = rowidx[r0];
            int g1 = rowidx[r0 + 8];
            if (g0 >= 0)
                *reinterpret_cast<float2*>(out + (size_t)g0 * DIN + col) =
                    make_float2(acc[s][nt][0] + bb0, acc[s][nt][1] + bb1);
            if (g1 >= 0)
                *reinterpret_cast<float2*>(out + (size_t)g1 * DIN + col) =
                    make_float2(acc[s][nt][2] + bb0, acc[s][nt][3] + bb1);
        }
    }
}

extern "C" void kernel_launch(void* const* d_in, const int* in_sizes, int n_in,
                              void* d_out, int out_size)
{
    const float* x     = (const float*)d_in[0];
    const float* W1    = (const float*)d_in[1];
    const float* b1    = (const float*)d_in[2];
    const float* W2    = (const float*)d_in[3];
    const float* b2    = (const float*)d_in[4];
    const int*   types = (const int*)  d_in[5];
    float*       out   = (float*)d_out;

    cudaFuncSetAttribute(mlp_kernel, cudaFuncAttributeMaxDynamicSharedMemorySize, SMEM_BYTES);

    prep_kernel<<<WELEMS / 256, 256>>>(W1, W2);
    scatter_kernel<<<NNODES / 256, 256>>>(types);
    plan_kernel<<<1, 32>>>();
    mlp_kernel<<<MAXWORK, 256, SMEM_BYTES>>>(x, b1, b2, out);
}